// round 1
// baseline (speedup 1.0000x reference)
#include <cuda_runtime.h>

#define Bb 2
#define Ss 2048
#define Dd 2048
#define Hh 16
#define HD 128
#define Mtot (Bb*Ss)

// Scratch (allocation-free rule: __device__ globals)
__device__ float g_Q[(size_t)Mtot * Dd];   // Q in [B,H,S,hd] layout
__device__ float g_A[(size_t)Mtot * Dd];   // attention output, merged [B,S,D]

// ---------------------------------------------------------------------------
// SGEMM: C = A[M,K] @ W[K,N] + bias[N]
// split==1: write C in [B,H,S,hd] layout (head-split of the [M,N] result)
// Tile: BM=BN=128, BK=8; 256 threads; 8x8 microtile, interleaved col mapping.
// ---------------------------------------------------------------------------
__global__ void gemm_kernel(const float* __restrict__ A, const float* __restrict__ W,
                            const float* __restrict__ bias, float* __restrict__ C,
                            int M, int N, int K, int split)
{
    __shared__ float As[8][128];
    __shared__ float Bs[8][128];

    const int bx = blockIdx.x;   // N tile
    const int by = blockIdx.y;   // M tile
    const int tid = threadIdx.x;
    const int tx = tid & 15;
    const int ty = tid >> 4;

    float acc[8][8];
#pragma unroll
    for (int i = 0; i < 8; i++)
#pragma unroll
        for (int j = 0; j < 8; j++) acc[i][j] = 0.f;

    const int arow = tid >> 1;          // 0..127
    const int acol = (tid & 1) * 4;     // 0 or 4
    const int brow = tid >> 5;          // 0..7
    const int bcol = (tid & 31) * 4;    // 0..124

    const float* Aptr = A + (size_t)(by * 128 + arow) * K + acol;
    const float* Bptr = W + (size_t)brow * N + bx * 128 + bcol;

    for (int k0 = 0; k0 < K; k0 += 8) {
        float4 av = *(const float4*)(Aptr + k0);
        float4 bv = *(const float4*)(Bptr + (size_t)k0 * N);
        As[acol + 0][arow] = av.x;
        As[acol + 1][arow] = av.y;
        As[acol + 2][arow] = av.z;
        As[acol + 3][arow] = av.w;
        *(float4*)&Bs[brow][bcol] = bv;
        __syncthreads();

#pragma unroll
        for (int kk = 0; kk < 8; kk++) {
            float ar[8], br[8];
#pragma unroll
            for (int i = 0; i < 8; i++) ar[i] = As[kk][ty + 16 * i];
#pragma unroll
            for (int j = 0; j < 8; j++) br[j] = Bs[kk][tx + 16 * j];
#pragma unroll
            for (int i = 0; i < 8; i++)
#pragma unroll
                for (int j = 0; j < 8; j++) acc[i][j] += ar[i] * br[j];
        }
        __syncthreads();
    }

#pragma unroll
    for (int i = 0; i < 8; i++) {
        int row = by * 128 + ty + 16 * i;
#pragma unroll
        for (int j = 0; j < 8; j++) {
            int col = bx * 128 + tx + 16 * j;
            float v = acc[i][j] + bias[col];
            if (split) {
                int b = row / Ss, s = row % Ss;
                int h = col / HD, d = col % HD;
                C[(((size_t)(b * Hh + h)) * Ss + s) * HD + d] = v;
            } else {
                C[(size_t)row * N + col] = v;
            }
        }
    }
}

// ---------------------------------------------------------------------------
// Flash-style causal attention, fp32.
// Grid: (S/64, B*H). Block: 256 threads. Q tile 64 rows, KV tiles 64 rows.
// Q/K/V layouts: [B,H,S,hd]. Output written merged: [B,S,D].
// ---------------------------------------------------------------------------
#define QSTR 129
#define KSTR 129
#define SSTR 65

__global__ void attn_kernel(const float* __restrict__ Q, const float* __restrict__ K,
                            const float* __restrict__ V, float* __restrict__ O)
{
    extern __shared__ float sm[];
    float* sQ = sm;                      // 64*129
    float* sK = sQ + 64 * QSTR;          // 64*129
    float* sV = sK + 64 * KSTR;          // 64*129
    float* sS = sV + 64 * KSTR;          // 64*65
    float* sM = sS + 64 * SSTR;          // 64
    float* sL = sM + 64;                 // 64
    float* sC = sL + 64;                 // 64

    const int qt = blockIdx.x;
    const int bh = blockIdx.y;
    const int tid = threadIdx.x;
    const int tx = tid & 15;
    const int ty = tid >> 4;

    const float* Qb = Q + ((size_t)bh * Ss + qt * 64) * HD;
    const float* Kb = K + (size_t)bh * Ss * HD;
    const float* Vb = V + (size_t)bh * Ss * HD;

    // Load Q tile (64x128) into padded shared
#pragma unroll
    for (int i = 0; i < 8; i++) {
        int idx = i * 256 + tid;         // 0..2047 float4 slots
        int col = idx >> 5;              // 0..63
        int d4 = (idx & 31) * 4;
        float4 qv = *(const float4*)(Qb + (size_t)col * HD + d4);
        float* qd = sQ + col * QSTR + d4;
        qd[0] = qv.x; qd[1] = qv.y; qd[2] = qv.z; qd[3] = qv.w;
    }
    if (tid < 64) { sM[tid] = -1e30f; sL[tid] = 0.f; }

    float o[4][8];
#pragma unroll
    for (int i = 0; i < 4; i++)
#pragma unroll
        for (int j = 0; j < 8; j++) o[i][j] = 0.f;

    const float scale = 0.08838834764831845f;  // 1/sqrt(128)

    for (int t = 0; t <= qt; t++) {
        __syncthreads();  // protect sK/sV reuse; also covers initial sQ/sM stores
        // Load K,V tiles (64x128 each)
#pragma unroll
        for (int i = 0; i < 8; i++) {
            int idx = i * 256 + tid;
            int col = idx >> 5;
            int d4 = (idx & 31) * 4;
            size_t goff = (size_t)(t * 64 + col) * HD + d4;
            float4 kv = *(const float4*)(Kb + goff);
            float4 vv = *(const float4*)(Vb + goff);
            float* kd = sK + col * KSTR + d4;
            kd[0] = kv.x; kd[1] = kv.y; kd[2] = kv.z; kd[3] = kv.w;
            float* vd = sV + col * KSTR + d4;
            vd[0] = vv.x; vd[1] = vv.y; vd[2] = vv.z; vd[3] = vv.w;
        }
        __syncthreads();

        // Scores: rows r=ty*4+i, cols c=tx+16*j (j<4)
        float s[4][4];
#pragma unroll
        for (int i = 0; i < 4; i++)
#pragma unroll
            for (int j = 0; j < 4; j++) s[i][j] = 0.f;

        for (int d = 0; d < 128; d++) {
            float qv[4], kv[4];
#pragma unroll
            for (int i = 0; i < 4; i++) qv[i] = sQ[(ty * 4 + i) * QSTR + d];
#pragma unroll
            for (int j = 0; j < 4; j++) kv[j] = sK[(tx + 16 * j) * KSTR + d];
#pragma unroll
            for (int i = 0; i < 4; i++)
#pragma unroll
                for (int j = 0; j < 4; j++) s[i][j] += qv[i] * kv[j];
        }

#pragma unroll
        for (int i = 0; i < 4; i++) {
#pragma unroll
            for (int j = 0; j < 4; j++) {
                float val = s[i][j] * scale;
                if (t == qt) {
                    int qg = ty * 4 + i;          // local row within diagonal tile
                    int kg = tx + 16 * j;         // local col
                    if (kg > qg) val = -1e30f;
                }
                sS[(ty * 4 + i) * SSTR + tx + 16 * j] = val;
            }
        }
        __syncthreads();

        // Online softmax: one thread per row
        if (tid < 64) {
            int r = tid;
            float m_old = sM[r];
            float mt = -1e30f;
            for (int k = 0; k < 64; k++) mt = fmaxf(mt, sS[r * SSTR + k]);
            float mn = fmaxf(m_old, mt);
            float corr = expf(m_old - mn);
            float l = sL[r] * corr;
            for (int k = 0; k < 64; k++) {
                float p = expf(sS[r * SSTR + k] - mn);
                sS[r * SSTR + k] = p;
                l += p;
            }
            sM[r] = mn; sL[r] = l; sC[r] = corr;
        }
        __syncthreads();

        // O update: O = O*corr + P @ V
        float corr_r[4];
#pragma unroll
        for (int i = 0; i < 4; i++) corr_r[i] = sC[ty * 4 + i];
#pragma unroll
        for (int i = 0; i < 4; i++)
#pragma unroll
            for (int j = 0; j < 8; j++) o[i][j] *= corr_r[i];

        for (int k = 0; k < 64; k++) {
            float p[4];
#pragma unroll
            for (int i = 0; i < 4; i++) p[i] = sS[(ty * 4 + i) * SSTR + k];
#pragma unroll
            for (int j = 0; j < 8; j++) {
                float vv = sV[k * KSTR + tx + 16 * j];
#pragma unroll
                for (int i = 0; i < 4; i++) o[i][j] += p[i] * vv;
            }
        }
    }

    // Epilogue: write merged [B,S,D]
    const int b = bh / Hh;
    const int h = bh % Hh;
#pragma unroll
    for (int i = 0; i < 4; i++) {
        int r = ty * 4 + i;
        float inv = 1.0f / sL[r];
        size_t base = ((size_t)b * Ss + qt * 64 + r) * Dd + h * HD;
#pragma unroll
        for (int j = 0; j < 8; j++) O[base + tx + 16 * j] = o[i][j] * inv;
    }
}

// ---------------------------------------------------------------------------

extern "C" void kernel_launch(void* const* d_in, const int* in_sizes, int n_in,
                              void* d_out, int out_size)
{
    const float* x  = (const float*)d_in[0];
    const float* Wq = (const float*)d_in[1];
    const float* bq = (const float*)d_in[2];
    const float* Wk = (const float*)d_in[3];
    const float* bk = (const float*)d_in[4];
    const float* Wv = (const float*)d_in[5];
    const float* bv = (const float*)d_in[6];
    const float* Wd = (const float*)d_in[7];
    const float* bd = (const float*)d_in[8];

    float* out = (float*)d_out;
    float* a_out = out;                            // [B,S,D]
    float* k_out = out + (size_t)Bb * Ss * Dd;     // present[0]: [B,H,S,hd]
    float* v_out = k_out + (size_t)Bb * Ss * Dd;   // present[1]: [B,H,S,hd]

    float *qs, *as;
    cudaGetSymbolAddress((void**)&qs, g_Q);
    cudaGetSymbolAddress((void**)&as, g_A);

    dim3 gg(Dd / 128, Mtot / 128);

    // QKV projections (K,V land directly in the `present` output region)
    gemm_kernel<<<gg, 256>>>(x, Wq, bq, qs,    Mtot, Dd, Dd, 1);
    gemm_kernel<<<gg, 256>>>(x, Wk, bk, k_out, Mtot, Dd, Dd, 1);
    gemm_kernel<<<gg, 256>>>(x, Wv, bv, v_out, Mtot, Dd, Dd, 1);

    // Attention
    size_t smem = (size_t)(64 * QSTR + 64 * KSTR * 2 + 64 * SSTR + 192) * sizeof(float);
    cudaFuncSetAttribute(attn_kernel, cudaFuncAttributeMaxDynamicSharedMemorySize, (int)smem);
    attn_kernel<<<dim3(Ss / 64, Bb * Hh), 256, smem>>>(qs, k_out, v_out, as);

    // Output projection
    gemm_kernel<<<gg, 256>>>(as, Wd, bd, a_out, Mtot, Dd, Dd, 0);
}

// round 2
// speedup vs baseline: 2.1775x; 2.1775x over previous
#include <cuda_runtime.h>
#include <cstdint>

#define Bb 2
#define Ss 2048
#define Dd 2048
#define Hh 16
#define HD 128
#define Mtot (Bb*Ss)

// Scratch (allocation-free rule: __device__ globals)
__device__ float g_Q[(size_t)Mtot * Dd];   // Q in [B,H,S,hd] layout
__device__ float g_A[(size_t)Mtot * Dd];   // attention output, merged [B,S,D]

__device__ __forceinline__ float to_tf32(float x) {
    float r;
    asm("cvt.rna.tf32.f32 %0, %1;" : "=f"(r) : "f"(x));
    return r;
}

// ---------------------------------------------------------------------------
// tf32 tensor-core SGEMM: C = A[M,K] @ W[K,N] + bias[N]
// BM=BN=128, BK=32. 256 threads = 8 warps (4m x 2n), warp tile 32x64.
// mma.sync.aligned.m16n8k8.row.col.f32.tf32.tf32.f32
// As[m][k] stride 36 (pad 4): conflict-free A-frag loads + STS.128.
// Bs[k][n] stride 136 (pad 8): conflict-free B-frag loads, no transpose.
// ---------------------------------------------------------------------------
#define ASTR 36
#define BSTR 136

__global__ __launch_bounds__(256, 2)
void gemm_tf32(const float* __restrict__ A, const float* __restrict__ W,
               const float* __restrict__ bias, float* __restrict__ C,
               int M, int N, int K, int split)
{
    __shared__ float As[128 * ASTR];
    __shared__ float Bs[32 * BSTR];

    const int tid  = threadIdx.x;
    const int lane = tid & 31;
    const int wid  = tid >> 5;
    const int wm   = wid >> 1;          // 0..3
    const int wn   = wid & 1;           // 0..1
    const int mb   = wm * 32;
    const int nb   = wn * 64;
    const int lr   = lane >> 2;         // 0..7
    const int lc   = lane & 3;          // 0..3
    const int bx   = blockIdx.x;
    const int by   = blockIdx.y;

    float acc[2][8][4];
#pragma unroll
    for (int f = 0; f < 2; f++)
#pragma unroll
        for (int g = 0; g < 8; g++)
#pragma unroll
            for (int t = 0; t < 4; t++) acc[f][g][t] = 0.f;

    // gmem->smem mappings
    const int am = (tid >> 1);               // unused style; real mapping below
    (void)am;

    for (int k0 = 0; k0 < K; k0 += 32) {
        // A tile: 128 x 32. idx -> m = idx>>3, c4 = (idx&7)*4. Coalesced.
#pragma unroll
        for (int i = 0; i < 4; i++) {
            int idx = i * 256 + tid;
            int m  = idx >> 3;
            int c4 = (idx & 7) * 4;
            float4 v = *(const float4*)(A + (size_t)(by * 128 + m) * K + k0 + c4);
            float* d = As + m * ASTR + c4;
            d[0] = to_tf32(v.x); d[1] = to_tf32(v.y);
            d[2] = to_tf32(v.z); d[3] = to_tf32(v.w);
        }
        // B tile: 32 x 128. idx -> kr = idx>>5, n4 = (idx&31)*4. Coalesced.
#pragma unroll
        for (int i = 0; i < 4; i++) {
            int idx = i * 256 + tid;
            int kr = idx >> 5;
            int n4 = (idx & 31) * 4;
            float4 v = *(const float4*)(W + (size_t)(k0 + kr) * N + bx * 128 + n4);
            float* d = Bs + kr * BSTR + n4;
            d[0] = to_tf32(v.x); d[1] = to_tf32(v.y);
            d[2] = to_tf32(v.z); d[3] = to_tf32(v.w);
        }
        __syncthreads();

#pragma unroll
        for (int s = 0; s < 4; s++) {
            const int ks = s * 8;
            uint32_t a[2][4], b[8][2];
#pragma unroll
            for (int f = 0; f < 2; f++) {
                const float* p = As + (mb + f * 16 + lr) * ASTR + ks + lc;
                a[f][0] = __float_as_uint(p[0]);
                a[f][1] = __float_as_uint(p[8 * ASTR]);
                a[f][2] = __float_as_uint(p[4]);
                a[f][3] = __float_as_uint(p[8 * ASTR + 4]);
            }
#pragma unroll
            for (int g = 0; g < 8; g++) {
                const float* p = Bs + (ks + lc) * BSTR + nb + g * 8 + lr;
                b[g][0] = __float_as_uint(p[0]);
                b[g][1] = __float_as_uint(p[4 * BSTR]);
            }
#pragma unroll
            for (int f = 0; f < 2; f++)
#pragma unroll
                for (int g = 0; g < 8; g++) {
                    asm volatile(
                        "mma.sync.aligned.m16n8k8.row.col.f32.tf32.tf32.f32 "
                        "{%0,%1,%2,%3}, {%4,%5,%6,%7}, {%8,%9}, {%0,%1,%2,%3};"
                        : "+f"(acc[f][g][0]), "+f"(acc[f][g][1]),
                          "+f"(acc[f][g][2]), "+f"(acc[f][g][3])
                        : "r"(a[f][0]), "r"(a[f][1]), "r"(a[f][2]), "r"(a[f][3]),
                          "r"(b[g][0]), "r"(b[g][1]));
                }
        }
        __syncthreads();
    }

    // Epilogue
#pragma unroll
    for (int f = 0; f < 2; f++) {
#pragma unroll
        for (int g = 0; g < 8; g++) {
#pragma unroll
            for (int ii = 0; ii < 2; ii++) {
                int row = by * 128 + mb + f * 16 + lr + 8 * ii;
#pragma unroll
                for (int jj = 0; jj < 2; jj++) {
                    int col = bx * 128 + nb + g * 8 + lc * 2 + jj;
                    float v = acc[f][g][ii * 2 + jj] + bias[col];
                    if (split) {
                        int b_ = row / Ss, s_ = row % Ss;
                        int h_ = col / HD, d_ = col % HD;
                        C[(((size_t)(b_ * Hh + h_)) * Ss + s_) * HD + d_] = v;
                    } else {
                        C[(size_t)row * N + col] = v;
                    }
                }
            }
        }
    }
}

// ---------------------------------------------------------------------------
// Flash-style causal attention, fp32.
// Grid: (S/64, B*H). Block: 256 threads. Q tile 64 rows, KV tiles 64 rows.
// smem trimmed to 113.25KB -> 2 blocks/SM. Row state (M/L/C) lives in the
// padding columns of sS (SSTR=67; cols 64..66).
// ---------------------------------------------------------------------------
#define QSTR 128
#define KSTR 129
#define SSTR 67

__global__ __launch_bounds__(256)
void attn_kernel(const float* __restrict__ Q, const float* __restrict__ K,
                 const float* __restrict__ V, float* __restrict__ O)
{
    extern __shared__ float sm[];
    float* sQ = sm;                      // 64*128
    float* sK = sQ + 64 * QSTR;          // 64*129
    float* sV = sK + 64 * KSTR;          // 64*129
    float* sS = sV + 64 * KSTR;          // 64*67 (cols 64..66 = M, L, C)

    const int qt = blockIdx.x;
    const int bh = blockIdx.y;
    const int tid = threadIdx.x;
    const int tx = tid & 15;
    const int ty = tid >> 4;

    const float* Qb = Q + ((size_t)bh * Ss + qt * 64) * HD;
    const float* Kb = K + (size_t)bh * Ss * HD;
    const float* Vb = V + (size_t)bh * Ss * HD;

    // Load Q tile (64x128)
#pragma unroll
    for (int i = 0; i < 8; i++) {
        int idx = i * 256 + tid;
        int col = idx >> 5;
        int d4 = (idx & 31) * 4;
        float4 qv = *(const float4*)(Qb + (size_t)col * HD + d4);
        float* qd = sQ + col * QSTR + d4;
        qd[0] = qv.x; qd[1] = qv.y; qd[2] = qv.z; qd[3] = qv.w;
    }
    if (tid < 64) { sS[tid * SSTR + 64] = -1e30f; sS[tid * SSTR + 65] = 0.f; }

    float o[4][8];
#pragma unroll
    for (int i = 0; i < 4; i++)
#pragma unroll
        for (int j = 0; j < 8; j++) o[i][j] = 0.f;

    const float scale = 0.08838834764831845f;  // 1/sqrt(128)

    for (int t = 0; t <= qt; t++) {
        __syncthreads();
#pragma unroll
        for (int i = 0; i < 8; i++) {
            int idx = i * 256 + tid;
            int col = idx >> 5;
            int d4 = (idx & 31) * 4;
            size_t goff = (size_t)(t * 64 + col) * HD + d4;
            float4 kv = *(const float4*)(Kb + goff);
            float4 vv = *(const float4*)(Vb + goff);
            float* kd = sK + col * KSTR + d4;
            kd[0] = kv.x; kd[1] = kv.y; kd[2] = kv.z; kd[3] = kv.w;
            float* vd = sV + col * KSTR + d4;
            vd[0] = vv.x; vd[1] = vv.y; vd[2] = vv.z; vd[3] = vv.w;
        }
        __syncthreads();

        float s[4][4];
#pragma unroll
        for (int i = 0; i < 4; i++)
#pragma unroll
            for (int j = 0; j < 4; j++) s[i][j] = 0.f;

        for (int d = 0; d < 128; d++) {
            float qv[4], kv[4];
#pragma unroll
            for (int i = 0; i < 4; i++) qv[i] = sQ[(ty * 4 + i) * QSTR + d];
#pragma unroll
            for (int j = 0; j < 4; j++) kv[j] = sK[(tx + 16 * j) * KSTR + d];
#pragma unroll
            for (int i = 0; i < 4; i++)
#pragma unroll
                for (int j = 0; j < 4; j++) s[i][j] += qv[i] * kv[j];
        }

#pragma unroll
        for (int i = 0; i < 4; i++) {
#pragma unroll
            for (int j = 0; j < 4; j++) {
                float val = s[i][j] * scale;
                if (t == qt) {
                    int qg = ty * 4 + i;
                    int kg = tx + 16 * j;
                    if (kg > qg) val = -1e30f;
                }
                sS[(ty * 4 + i) * SSTR + tx + 16 * j] = val;
            }
        }
        __syncthreads();

        // Online softmax: one thread per row (conflict-free: bank = 3r+k)
        if (tid < 64) {
            int r = tid;
            float m_old = sS[r * SSTR + 64];
            float mt = -1e30f;
            for (int k = 0; k < 64; k++) mt = fmaxf(mt, sS[r * SSTR + k]);
            float mn = fmaxf(m_old, mt);
            float corr = expf(m_old - mn);
            float l = sS[r * SSTR + 65] * corr;
            for (int k = 0; k < 64; k++) {
                float p = expf(sS[r * SSTR + k] - mn);
                sS[r * SSTR + k] = p;
                l += p;
            }
            sS[r * SSTR + 64] = mn;
            sS[r * SSTR + 65] = l;
            sS[r * SSTR + 66] = corr;
        }
        __syncthreads();

        float corr_r[4];
#pragma unroll
        for (int i = 0; i < 4; i++) corr_r[i] = sS[(ty * 4 + i) * SSTR + 66];
#pragma unroll
        for (int i = 0; i < 4; i++)
#pragma unroll
            for (int j = 0; j < 8; j++) o[i][j] *= corr_r[i];

        for (int k = 0; k < 64; k++) {
            float p[4];
#pragma unroll
            for (int i = 0; i < 4; i++) p[i] = sS[(ty * 4 + i) * SSTR + k];
#pragma unroll
            for (int j = 0; j < 8; j++) {
                float vv = sV[k * KSTR + tx + 16 * j];
#pragma unroll
                for (int i = 0; i < 4; i++) o[i][j] += p[i] * vv;
            }
        }
    }

    const int b = bh / Hh;
    const int h = bh % Hh;
#pragma unroll
    for (int i = 0; i < 4; i++) {
        int r = ty * 4 + i;
        float inv = 1.0f / sS[r * SSTR + 65];
        size_t base = ((size_t)b * Ss + qt * 64 + r) * Dd + h * HD;
#pragma unroll
        for (int j = 0; j < 8; j++) O[base + tx + 16 * j] = o[i][j] * inv;
    }
}

// ---------------------------------------------------------------------------

extern "C" void kernel_launch(void* const* d_in, const int* in_sizes, int n_in,
                              void* d_out, int out_size)
{
    const float* x  = (const float*)d_in[0];
    const float* Wq = (const float*)d_in[1];
    const float* bq = (const float*)d_in[2];
    const float* Wk = (const float*)d_in[3];
    const float* bk = (const float*)d_in[4];
    const float* Wv = (const float*)d_in[5];
    const float* bv = (const float*)d_in[6];
    const float* Wd = (const float*)d_in[7];
    const float* bd = (const float*)d_in[8];

    float* out = (float*)d_out;
    float* a_out = out;                            // [B,S,D]
    float* k_out = out + (size_t)Bb * Ss * Dd;     // present[0]: [B,H,S,hd]
    float* v_out = k_out + (size_t)Bb * Ss * Dd;   // present[1]: [B,H,S,hd]

    float *qs, *as;
    cudaGetSymbolAddress((void**)&qs, g_Q);
    cudaGetSymbolAddress((void**)&as, g_A);

    dim3 gg(Dd / 128, Mtot / 128);

    // QKV projections (K,V land directly in the `present` output region)
    gemm_tf32<<<gg, 256>>>(x, Wq, bq, qs,    Mtot, Dd, Dd, 1);
    gemm_tf32<<<gg, 256>>>(x, Wk, bk, k_out, Mtot, Dd, Dd, 1);
    gemm_tf32<<<gg, 256>>>(x, Wv, bv, v_out, Mtot, Dd, Dd, 1);

    // Attention
    size_t smem = (size_t)(64 * QSTR + 64 * KSTR * 2 + 64 * SSTR) * sizeof(float);
    cudaFuncSetAttribute(attn_kernel, cudaFuncAttributeMaxDynamicSharedMemorySize, (int)smem);
    attn_kernel<<<dim3(Ss / 64, Bb * Hh), 256, smem>>>(qs, k_out, v_out, as);

    // Output projection
    gemm_tf32<<<gg, 256>>>(as, Wd, bd, a_out, Mtot, Dd, Dd, 0);
}

// round 3
// speedup vs baseline: 2.8693x; 1.3177x over previous
#include <cuda_runtime.h>
#include <cstdint>

#define Bb 2
#define Ss 2048
#define Dd 2048
#define Hh 16
#define HD 128
#define Mtot (Bb*Ss)

__device__ float g_Q[(size_t)Mtot * Dd];   // Q in [B,H,S,hd] layout
__device__ float g_A[(size_t)Mtot * Dd];   // attention output, merged [B,S,D]

__device__ __forceinline__ float to_tf32(float x) {
    float r;
    asm("cvt.rna.tf32.f32 %0, %1;" : "=f"(r) : "f"(x));
    return r;
}

// Split fp32 into tf32 hi + tf32 lo (hi = truncated top 11 bits of significand)
__device__ __forceinline__ void split_tf32(float x, uint32_t& hi, uint32_t& lo) {
    uint32_t h = __float_as_uint(x) & 0xffffe000u;
    hi = h;
    float l = x - __uint_as_float(h);
    asm("cvt.rna.tf32.f32 %0, %1;" : "=r"(lo) : "f"(l));
}

__device__ __forceinline__ void mma8(float* c, const uint32_t* a, const uint32_t* b) {
    asm volatile(
        "mma.sync.aligned.m16n8k8.row.col.f32.tf32.tf32.f32 "
        "{%0,%1,%2,%3}, {%4,%5,%6,%7}, {%8,%9}, {%0,%1,%2,%3};"
        : "+f"(c[0]), "+f"(c[1]), "+f"(c[2]), "+f"(c[3])
        : "r"(a[0]), "r"(a[1]), "r"(a[2]), "r"(a[3]), "r"(b[0]), "r"(b[1]));
}

__device__ __forceinline__ void cpa16(void* dst, const void* src) {
    uint32_t d = (uint32_t)__cvta_generic_to_shared(dst);
    asm volatile("cp.async.cg.shared.global [%0], [%1], 16;" :: "r"(d), "l"(src));
}
#define CP_COMMIT asm volatile("cp.async.commit_group;")
#define CP_WAIT1  asm volatile("cp.async.wait_group 1;")
#define CP_WAIT0  asm volatile("cp.async.wait_group 0;")

// ---------------------------------------------------------------------------
// tf32 tensor-core SGEMM (unchanged from R1): C = A @ W + bias
// ---------------------------------------------------------------------------
#define ASTR 36
#define BSTR 136

__global__ __launch_bounds__(256, 2)
void gemm_tf32(const float* __restrict__ A, const float* __restrict__ W,
               const float* __restrict__ bias, float* __restrict__ C,
               int M, int N, int K, int split)
{
    __shared__ float As[128 * ASTR];
    __shared__ float Bs[32 * BSTR];

    const int tid  = threadIdx.x;
    const int lane = tid & 31;
    const int wid  = tid >> 5;
    const int wm   = wid >> 1;
    const int wn   = wid & 1;
    const int mb   = wm * 32;
    const int nb   = wn * 64;
    const int lr   = lane >> 2;
    const int lc   = lane & 3;
    const int bx   = blockIdx.x;
    const int by   = blockIdx.y;

    float acc[2][8][4];
#pragma unroll
    for (int f = 0; f < 2; f++)
#pragma unroll
        for (int g = 0; g < 8; g++)
#pragma unroll
            for (int t = 0; t < 4; t++) acc[f][g][t] = 0.f;

    for (int k0 = 0; k0 < K; k0 += 32) {
#pragma unroll
        for (int i = 0; i < 4; i++) {
            int idx = i * 256 + tid;
            int m  = idx >> 3;
            int c4 = (idx & 7) * 4;
            float4 v = *(const float4*)(A + (size_t)(by * 128 + m) * K + k0 + c4);
            float* d = As + m * ASTR + c4;
            d[0] = to_tf32(v.x); d[1] = to_tf32(v.y);
            d[2] = to_tf32(v.z); d[3] = to_tf32(v.w);
        }
#pragma unroll
        for (int i = 0; i < 4; i++) {
            int idx = i * 256 + tid;
            int kr = idx >> 5;
            int n4 = (idx & 31) * 4;
            float4 v = *(const float4*)(W + (size_t)(k0 + kr) * N + bx * 128 + n4);
            float* d = Bs + kr * BSTR + n4;
            d[0] = to_tf32(v.x); d[1] = to_tf32(v.y);
            d[2] = to_tf32(v.z); d[3] = to_tf32(v.w);
        }
        __syncthreads();

#pragma unroll
        for (int s = 0; s < 4; s++) {
            const int ks = s * 8;
            uint32_t a[2][4], b[8][2];
#pragma unroll
            for (int f = 0; f < 2; f++) {
                const float* p = As + (mb + f * 16 + lr) * ASTR + ks + lc;
                a[f][0] = __float_as_uint(p[0]);
                a[f][1] = __float_as_uint(p[8 * ASTR]);
                a[f][2] = __float_as_uint(p[4]);
                a[f][3] = __float_as_uint(p[8 * ASTR + 4]);
            }
#pragma unroll
            for (int g = 0; g < 8; g++) {
                const float* p = Bs + (ks + lc) * BSTR + nb + g * 8 + lr;
                b[g][0] = __float_as_uint(p[0]);
                b[g][1] = __float_as_uint(p[4 * BSTR]);
            }
#pragma unroll
            for (int f = 0; f < 2; f++)
#pragma unroll
                for (int g = 0; g < 8; g++) mma8(acc[f][g], a[f], b[g]);
        }
        __syncthreads();
    }

#pragma unroll
    for (int f = 0; f < 2; f++) {
#pragma unroll
        for (int g = 0; g < 8; g++) {
#pragma unroll
            for (int ii = 0; ii < 2; ii++) {
                int row = by * 128 + mb + f * 16 + lr + 8 * ii;
#pragma unroll
                for (int jj = 0; jj < 2; jj++) {
                    int col = bx * 128 + nb + g * 8 + lc * 2 + jj;
                    float v = acc[f][g][ii * 2 + jj] + bias[col];
                    if (split) {
                        int b_ = row / Ss, s_ = row % Ss;
                        int h_ = col / HD, d_ = col % HD;
                        C[(((size_t)(b_ * Hh + h_)) * Ss + s_) * HD + d_] = v;
                    } else {
                        C[(size_t)row * N + col] = v;
                    }
                }
            }
        }
    }
}

// ---------------------------------------------------------------------------
// Tensor-core flash attention (split-tf32, fp32-accurate).
// Grid: (S/128, B*H). 256 threads = 8 warps, each warp owns 16 q-rows.
// KV tiles of 64, cp.async double-buffered.
// ---------------------------------------------------------------------------
#define QS 132
#define KSTRD 132
#define VSTRD 136
#define SQ_ELE (128 * QS)
#define SK_ELE (64 * KSTRD)
#define SV_ELE (64 * VSTRD)

__global__ __launch_bounds__(256)
void attn_tc(const float* __restrict__ Q, const float* __restrict__ K,
             const float* __restrict__ V, float* __restrict__ O)
{
    extern __shared__ float sm[];
    float* sQ = sm;                          // 128 x 132
    float* sK = sQ + SQ_ELE;                 // 2 x 64 x 132
    float* sV = sK + 2 * SK_ELE;             // 2 x 64 x 136

    const int qt  = (gridDim.x - 1) - blockIdx.x;   // big blocks first
    const int bh  = blockIdx.y;
    const int tid = threadIdx.x;
    const int lane = tid & 31;
    const int wid  = tid >> 5;
    const int lr   = lane >> 2;      // 0..7
    const int lc   = lane & 3;       // 0..3
    const int m_off = wid * 16;

    const float* Qb = Q + ((size_t)bh * Ss + (size_t)qt * 128) * HD;
    const float* Kb = K + (size_t)bh * Ss * HD;
    const float* Vb = V + (size_t)bh * Ss * HD;

    // Async-load Q tile (128x128)
#pragma unroll
    for (int i = 0; i < 16; i++) {
        int idx = i * 256 + tid;
        int row = idx >> 5;
        int c4  = (idx & 31) * 4;
        cpa16(sQ + row * QS + c4, Qb + (size_t)row * HD + c4);
    }
    // Async-load KV tile 0 into buffer 0
    {
#pragma unroll
        for (int i = 0; i < 8; i++) {
            int idx = i * 256 + tid;
            int row = idx >> 5;
            int c4  = (idx & 31) * 4;
            cpa16(sK + row * KSTRD + c4, Kb + (size_t)row * HD + c4);
            cpa16(sV + row * VSTRD + c4, Vb + (size_t)row * HD + c4);
        }
    }
    CP_COMMIT;

    float o[16][4];
#pragma unroll
    for (int n = 0; n < 16; n++)
#pragma unroll
        for (int j = 0; j < 4; j++) o[n][j] = 0.f;
    float m0 = -1e30f, m1 = -1e30f, l0 = 0.f, l1 = 0.f;

    const float scale = 0.08838834764831845f;  // 1/sqrt(128)
    const int tmax = 2 * qt + 1;

    for (int t = 0; t <= tmax; t++) {
        const int buf = t & 1;
        if (t < tmax) {
            const int nb2 = (t + 1) & 1;
            float* dK = sK + nb2 * SK_ELE;
            float* dV = sV + nb2 * SV_ELE;
            const float* gK = Kb + (size_t)(t + 1) * 64 * HD;
            const float* gV = Vb + (size_t)(t + 1) * 64 * HD;
#pragma unroll
            for (int i = 0; i < 8; i++) {
                int idx = i * 256 + tid;
                int row = idx >> 5;
                int c4  = (idx & 31) * 4;
                cpa16(dK + row * KSTRD + c4, gK + (size_t)row * HD + c4);
                cpa16(dV + row * VSTRD + c4, gV + (size_t)row * HD + c4);
            }
            CP_COMMIT;
            CP_WAIT1;
        } else {
            CP_WAIT0;
        }
        __syncthreads();

        const float* sKb = sK + buf * SK_ELE;
        const float* sVb = sV + buf * SV_ELE;

        // ---- S = Q @ K^T (3-pass split tf32), warp tile 16x64 ----
        float c[8][4];
#pragma unroll
        for (int n = 0; n < 8; n++)
#pragma unroll
            for (int j = 0; j < 4; j++) c[n][j] = 0.f;

#pragma unroll
        for (int ks = 0; ks < 16; ks++) {
            const int k0 = ks * 8;
            const float* qp = sQ + (m_off + lr) * QS + k0 + lc;
            float qa0 = qp[0], qa1 = qp[8 * QS], qa2 = qp[4], qa3 = qp[8 * QS + 4];
            uint32_t ah[4], al[4];
            split_tf32(qa0, ah[0], al[0]);
            split_tf32(qa1, ah[1], al[1]);
            split_tf32(qa2, ah[2], al[2]);
            split_tf32(qa3, ah[3], al[3]);
#pragma unroll
            for (int nf = 0; nf < 8; nf++) {
                const float* kp = sKb + (nf * 8 + lr) * KSTRD + k0 + lc;
                uint32_t bhh[2], bll[2];
                split_tf32(kp[0], bhh[0], bll[0]);
                split_tf32(kp[4], bhh[1], bll[1]);
                mma8(c[nf], ah, bhh);
                mma8(c[nf], al, bhh);
                mma8(c[nf], ah, bll);
            }
        }

        // ---- scale + causal mask ----
#pragma unroll
        for (int nf = 0; nf < 8; nf++)
#pragma unroll
            for (int j = 0; j < 4; j++) c[nf][j] *= scale;

        if (t * 64 + 63 > qt * 128 + m_off) {
#pragma unroll
            for (int nf = 0; nf < 8; nf++) {
#pragma unroll
                for (int j = 0; j < 4; j++) {
                    int col = t * 64 + nf * 8 + 2 * lc + (j & 1);
                    int row = qt * 128 + m_off + lr + 8 * (j >> 1);
                    if (col > row) c[nf][j] = -1e30f;
                }
            }
        }

        // ---- online softmax (warp-local, rows lr and lr+8) ----
        float mt0 = -1e30f, mt1 = -1e30f;
#pragma unroll
        for (int nf = 0; nf < 8; nf++) {
            mt0 = fmaxf(mt0, fmaxf(c[nf][0], c[nf][1]));
            mt1 = fmaxf(mt1, fmaxf(c[nf][2], c[nf][3]));
        }
#pragma unroll
        for (int d = 1; d <= 2; d <<= 1) {
            mt0 = fmaxf(mt0, __shfl_xor_sync(0xffffffffu, mt0, d));
            mt1 = fmaxf(mt1, __shfl_xor_sync(0xffffffffu, mt1, d));
        }
        float nm0 = fmaxf(m0, mt0), nm1 = fmaxf(m1, mt1);
        float corr0 = __expf(m0 - nm0), corr1 = __expf(m1 - nm1);
        m0 = nm0; m1 = nm1;

        float s0 = 0.f, s1 = 0.f;
#pragma unroll
        for (int nf = 0; nf < 8; nf++) {
            c[nf][0] = __expf(c[nf][0] - nm0); s0 += c[nf][0];
            c[nf][1] = __expf(c[nf][1] - nm0); s0 += c[nf][1];
            c[nf][2] = __expf(c[nf][2] - nm1); s1 += c[nf][2];
            c[nf][3] = __expf(c[nf][3] - nm1); s1 += c[nf][3];
        }
#pragma unroll
        for (int d = 1; d <= 2; d <<= 1) {
            s0 += __shfl_xor_sync(0xffffffffu, s0, d);
            s1 += __shfl_xor_sync(0xffffffffu, s1, d);
        }
        l0 = l0 * corr0 + s0;
        l1 = l1 * corr1 + s1;

#pragma unroll
        for (int n = 0; n < 16; n++) {
            o[n][0] *= corr0; o[n][1] *= corr0;
            o[n][2] *= corr1; o[n][3] *= corr1;
        }

        // ---- O += P @ V (3-pass split tf32), warp tile 16x128 ----
#pragma unroll
        for (int ks = 0; ks < 8; ks++) {
            // gather P A-fragments from c[ks][...] via shfl
            const int src0 = 4 * lr + (lc >> 1);
            const int src1 = src0 + 2;
            float v00 = __shfl_sync(0xffffffffu, c[ks][0], src0);
            float v01 = __shfl_sync(0xffffffffu, c[ks][1], src0);
            float v20 = __shfl_sync(0xffffffffu, c[ks][2], src0);
            float v21 = __shfl_sync(0xffffffffu, c[ks][3], src0);
            float w00 = __shfl_sync(0xffffffffu, c[ks][0], src1);
            float w01 = __shfl_sync(0xffffffffu, c[ks][1], src1);
            float w20 = __shfl_sync(0xffffffffu, c[ks][2], src1);
            float w21 = __shfl_sync(0xffffffffu, c[ks][3], src1);
            float a0f = (lc & 1) ? v01 : v00;
            float a1f = (lc & 1) ? v21 : v20;
            float a2f = (lc & 1) ? w01 : w00;
            float a3f = (lc & 1) ? w21 : w20;
            uint32_t ah[4], al[4];
            split_tf32(a0f, ah[0], al[0]);
            split_tf32(a1f, ah[1], al[1]);
            split_tf32(a2f, ah[2], al[2]);
            split_tf32(a3f, ah[3], al[3]);
#pragma unroll
            for (int nf = 0; nf < 16; nf++) {
                const float* vp = sVb + (ks * 8 + lc) * VSTRD + nf * 8 + lr;
                uint32_t bhh[2], bll[2];
                split_tf32(vp[0], bhh[0], bll[0]);
                split_tf32(vp[4 * VSTRD], bhh[1], bll[1]);
                mma8(o[nf], ah, bhh);
                mma8(o[nf], al, bhh);
                mma8(o[nf], ah, bll);
            }
        }
        __syncthreads();
    }

    // ---- epilogue: normalize and write merged [B,S,D] ----
    const float inv0 = 1.0f / l0;
    const float inv1 = 1.0f / l1;
    const int b = bh / Hh;
    const int h = bh % Hh;
    const int row0 = qt * 128 + m_off + lr;
    const int row1 = row0 + 8;
    float* p0 = O + ((size_t)b * Ss + row0) * Dd + h * HD + 2 * lc;
    float* p1 = O + ((size_t)b * Ss + row1) * Dd + h * HD + 2 * lc;
#pragma unroll
    for (int nf = 0; nf < 16; nf++) {
        float2 r0 = make_float2(o[nf][0] * inv0, o[nf][1] * inv0);
        float2 r1 = make_float2(o[nf][2] * inv1, o[nf][3] * inv1);
        *(float2*)(p0 + nf * 8) = r0;
        *(float2*)(p1 + nf * 8) = r1;
    }
}

// ---------------------------------------------------------------------------

extern "C" void kernel_launch(void* const* d_in, const int* in_sizes, int n_in,
                              void* d_out, int out_size)
{
    const float* x  = (const float*)d_in[0];
    const float* Wq = (const float*)d_in[1];
    const float* bq = (const float*)d_in[2];
    const float* Wk = (const float*)d_in[3];
    const float* bk = (const float*)d_in[4];
    const float* Wv = (const float*)d_in[5];
    const float* bv = (const float*)d_in[6];
    const float* Wd = (const float*)d_in[7];
    const float* bd = (const float*)d_in[8];

    float* out = (float*)d_out;
    float* a_out = out;                            // [B,S,D]
    float* k_out = out + (size_t)Bb * Ss * Dd;     // present[0]
    float* v_out = k_out + (size_t)Bb * Ss * Dd;   // present[1]

    float *qs, *as;
    cudaGetSymbolAddress((void**)&qs, g_Q);
    cudaGetSymbolAddress((void**)&as, g_A);

    dim3 gg(Dd / 128, Mtot / 128);

    gemm_tf32<<<gg, 256>>>(x, Wq, bq, qs,    Mtot, Dd, Dd, 1);
    gemm_tf32<<<gg, 256>>>(x, Wk, bk, k_out, Mtot, Dd, Dd, 1);
    gemm_tf32<<<gg, 256>>>(x, Wv, bv, v_out, Mtot, Dd, Dd, 1);

    size_t smem = (size_t)(SQ_ELE + 2 * SK_ELE + 2 * SV_ELE) * sizeof(float);
    cudaFuncSetAttribute(attn_tc, cudaFuncAttributeMaxDynamicSharedMemorySize, (int)smem);
    attn_tc<<<dim3(Ss / 128, Bb * Hh), 256, smem>>>(qs, k_out, v_out, as);

    gemm_tf32<<<gg, 256>>>(as, Wd, bd, a_out, Mtot, Dd, Dd, 0);
}

// round 4
// speedup vs baseline: 3.9530x; 1.3777x over previous
#include <cuda_runtime.h>
#include <cstdint>

#define Bb 2
#define Ss 2048
#define Dd 2048
#define Hh 16
#define HD 128
#define Mtot (Bb*Ss)

// Paired-tf32 global scratch.
// XP/AP: [Mtot][2048] floats, row m, k-pairs: float addr = m*2048 + (k>>3)*8 + (k&3)*2 + ((k>>2)&1)
// WP:    [K/8][N][4 float2]:          addr = (k>>3)*16384 + n*8 + (k&3)*2 + ((k>>2)&1)
// QP/KP: per bh [Ss][128]:            addr = (bh*Ss+s)*128 + (d>>3)*8 + (d&3)*2 + ((d>>2)&1)
// VP:    per bh [128 d][2048]:        addr = (bh*128+d)*2048 + (s>>3)*8 + (s&3)*2 + ((s>>2)&1)
__device__ float g_XP[(size_t)Mtot * Dd];
__device__ float g_WPq[(size_t)Dd * Dd];
__device__ float g_WPk[(size_t)Dd * Dd];
__device__ float g_WPv[(size_t)Dd * Dd];
__device__ float g_WPd[(size_t)Dd * Dd];
__device__ float g_QP[(size_t)Mtot * Dd];
__device__ float g_KP[(size_t)Mtot * Dd];
__device__ float g_VP[(size_t)Mtot * Dd];
__device__ float g_AP[(size_t)Mtot * Dd];

__device__ __forceinline__ float to_tf32(float x) {
    float r;
    asm("cvt.rna.tf32.f32 %0, %1;" : "=f"(r) : "f"(x));
    return r;
}
__device__ __forceinline__ uint32_t u32(float x) { return __float_as_uint(x); }

__device__ __forceinline__ void mma8(float* c, const uint32_t* a, const uint32_t* b) {
    asm volatile(
        "mma.sync.aligned.m16n8k8.row.col.f32.tf32.tf32.f32 "
        "{%0,%1,%2,%3}, {%4,%5,%6,%7}, {%8,%9}, {%0,%1,%2,%3};"
        : "+f"(c[0]), "+f"(c[1]), "+f"(c[2]), "+f"(c[3])
        : "r"(a[0]), "r"(a[1]), "r"(a[2]), "r"(a[3]), "r"(b[0]), "r"(b[1]));
}
__device__ __forceinline__ void cpa16(void* dst, const void* src) {
    uint32_t d = (uint32_t)__cvta_generic_to_shared(dst);
    asm volatile("cp.async.cg.shared.global [%0], [%1], 16;" :: "r"(d), "l"(src));
}
#define CP_COMMIT asm volatile("cp.async.commit_group;")
#define CP_WAIT1  asm volatile("cp.async.wait_group 1;")
#define CP_WAIT0  asm volatile("cp.async.wait_group 0;")

// ---------------------------------------------------------------------------
// Prep: x -> paired tf32 (XP format)
// ---------------------------------------------------------------------------
__global__ void xprep(const float* __restrict__ X, float* __restrict__ XP) {
    size_t i = (size_t)blockIdx.x * 256 + threadIdx.x;   // over Mtot*Dd/4
    int m  = (int)(i >> 9);
    int k0 = ((int)i & 511) * 4;
    float4 v = *(const float4*)(X + (size_t)m * 2048 + k0);
    float vv[4] = {v.x, v.y, v.z, v.w};
#pragma unroll
    for (int j = 0; j < 4; j++) {
        int k = k0 + j;
        XP[(size_t)m * 2048 + (k >> 3) * 8 + (k & 3) * 2 + ((k >> 2) & 1)] = to_tf32(vv[j]);
    }
}

// Prep: W[K][N] -> WP paired tf32
__global__ void wprep(const float* __restrict__ W, float* __restrict__ WP) {
    size_t i = (size_t)blockIdx.x * 256 + threadIdx.x;   // over Dd*Dd/4
    int k  = (int)(i >> 9);
    int n0 = ((int)i & 511) * 4;
    float4 v = *(const float4*)(W + (size_t)k * 2048 + n0);
    float vv[4] = {v.x, v.y, v.z, v.w};
#pragma unroll
    for (int j = 0; j < 4; j++) {
        WP[(size_t)(k >> 3) * 16384 + (size_t)(n0 + j) * 8 + (k & 3) * 2 + ((k >> 2) & 1)]
            = to_tf32(vv[j]);
    }
}

// ---------------------------------------------------------------------------
// Pipelined tf32 tensor-core GEMM on pre-paired operands.
// BM=BN=128, BK=32, 256 thr = 8 warps (4m x 2n), warp 32x64.
// As: [128 m][20 float2] (16 used + pad, stride 40 x 4B = 8 mod 32 -> CF)
// Bs: [4 kb][128 n][4 float2]
// modes: 0=plain C fp32; 1=Q->QP; 2=K->k_out+KP; 3=V->v_out+VP
// ---------------------------------------------------------------------------
#define ABUF2 (128*20)
#define BBUF2 (4*128*4)
#define GBUF2 (ABUF2 + BBUF2)

__global__ __launch_bounds__(256, 2)
void gemm_tc(const float* __restrict__ Ap, const float* __restrict__ WP,
             const float* __restrict__ bias, float* __restrict__ Craw,
             float* __restrict__ Cpair, int mode)
{
    extern __shared__ float2 sm2[];

    const int tid  = threadIdx.x;
    const int lane = tid & 31;
    const int wid  = tid >> 5;
    const int mb   = (wid >> 1) * 32;
    const int nb   = (wid & 1) * 64;
    const int lr   = lane >> 2;
    const int lc   = lane & 3;
    const int bx   = blockIdx.x;
    const int by   = blockIdx.y;

    float acc[2][8][4];
#pragma unroll
    for (int f = 0; f < 2; f++)
#pragma unroll
        for (int g = 0; g < 8; g++)
#pragma unroll
            for (int t = 0; t < 4; t++) acc[f][g][t] = 0.f;

    // per-thread load mapping
    const int a_m  = tid >> 1;               // 0..127 over 2 iters? (use idx loop)
    (void)a_m;

    // issue tile kt into buffer
    auto issue = [&](int kt, int buf) {
        float2* As = sm2 + buf * GBUF2;
        float2* Bs = As + ABUF2;
#pragma unroll
        for (int j = 0; j < 4; j++) {
            int idx = j * 256 + tid;         // 0..1023
            int m   = idx >> 3;
            int ch  = idx & 7;
            cpa16(As + m * 20 + ch * 2,
                  Ap + (size_t)(by * 128 + m) * 2048 + kt * 32 + ch * 4);
        }
#pragma unroll
        for (int j = 0; j < 4; j++) {
            int idx = j * 256 + tid;
            int kb  = idx >> 8;
            int r   = idx & 255;
            int n   = r >> 1;
            int ch  = r & 1;
            cpa16(Bs + kb * 512 + n * 4 + ch * 2,
                  WP + (size_t)(kt * 4 + kb) * 16384 + (size_t)(bx * 128 + n) * 8 + ch * 4);
        }
    };

    issue(0, 0);
    CP_COMMIT;

    for (int kt = 0; kt < 64; kt++) {
        CP_WAIT0;
        __syncthreads();
        if (kt < 63) { issue(kt + 1, (kt + 1) & 1); CP_COMMIT; }

        const float2* As = sm2 + (kt & 1) * GBUF2;
        const float2* Bs = As + ABUF2;

#pragma unroll
        for (int ks = 0; ks < 4; ks++) {
            const float2* ap = As + (mb + lr) * 20 + ks * 4 + lc;
            float2 x00 = ap[0], x01 = ap[160], x10 = ap[320], x11 = ap[480];
            uint32_t a0[4] = {u32(x00.x), u32(x01.x), u32(x00.y), u32(x01.y)};
            uint32_t a1[4] = {u32(x10.x), u32(x11.x), u32(x10.y), u32(x11.y)};
            const float2* bp = Bs + ks * 512 + (nb + lr) * 4 + lc;
#pragma unroll
            for (int g = 0; g < 8; g++) {
                float2 bv = bp[g * 32];
                uint32_t b[2] = {u32(bv.x), u32(bv.y)};
                mma8(acc[0][g], a0, b);
                mma8(acc[1][g], a1, b);
            }
        }
        __syncthreads();
    }

    // epilogue
#pragma unroll
    for (int f = 0; f < 2; f++) {
#pragma unroll
        for (int g = 0; g < 8; g++) {
#pragma unroll
            for (int ii = 0; ii < 2; ii++) {
                int row = by * 128 + mb + f * 16 + lr + 8 * ii;
#pragma unroll
                for (int jj = 0; jj < 2; jj++) {
                    int col = bx * 128 + nb + g * 8 + lc * 2 + jj;
                    float v = acc[f][g][ii * 2 + jj] + bias[col];
                    if (mode == 0) {
                        Craw[(size_t)row * Dd + col] = v;
                    } else {
                        int b_ = row >> 11, s_ = row & 2047;
                        int h_ = col >> 7,  d_ = col & 127;
                        size_t bh = (size_t)(b_ * Hh + h_);
                        if (mode >= 2) Craw[(bh * Ss + s_) * HD + d_] = v;
                        float tv = to_tf32(v);
                        if (mode == 3) {
                            Cpair[(bh * 128 + d_) * 2048 +
                                  (s_ >> 3) * 8 + (s_ & 3) * 2 + ((s_ >> 2) & 1)] = tv;
                        } else {
                            Cpair[(bh * Ss + s_) * 128 +
                                  (d_ >> 3) * 8 + (d_ & 3) * 2 + ((d_ >> 2) & 1)] = tv;
                        }
                    }
                }
            }
        }
    }
}

// ---------------------------------------------------------------------------
// Single-pass tf32 flash attention on pre-paired operands.
// Grid (S/128, B*H), 256 thr = 8 warps x 16 q-rows. KV tiles 64, double-buffered.
// sQP: [128][68 f2]  sKP: 2x[64][68 f2]  sVP: 2x[128 d][36 f2]
// Output written pre-paired tf32 to AP for the final GEMM.
// ---------------------------------------------------------------------------
#define QS2 68
#define KS2 68
#define VS2 36
#define SQ2 (128*QS2)
#define SK2 (64*KS2)
#define SV2 (128*VS2)

__global__ __launch_bounds__(256)
void attn_tc(const float* __restrict__ QP, const float* __restrict__ KP,
             const float* __restrict__ VP, float* __restrict__ AP)
{
    extern __shared__ float2 sm2[];
    float2* sQ = sm2;                  // SQ2
    float2* sK = sQ + SQ2;             // 2*SK2
    float2* sV = sK + 2 * SK2;         // 2*SV2

    const int qt  = (gridDim.x - 1) - blockIdx.x;
    const int bh  = blockIdx.y;
    const int tid = threadIdx.x;
    const int lane = tid & 31;
    const int wid  = tid >> 5;
    const int lr   = lane >> 2;
    const int lc   = lane & 3;
    const int m_off = wid * 16;

    const float* Qg = QP + ((size_t)bh * Ss + (size_t)qt * 128) * 128;
    const float* Kg = KP + (size_t)bh * Ss * 128;
    const float* Vg = VP + (size_t)bh * 128 * 2048;

    // Q tile: 128 rows x 128 floats
#pragma unroll
    for (int i = 0; i < 16; i++) {
        int idx = i * 256 + tid;
        int row = idx >> 5;
        int ch  = idx & 31;
        cpa16(sQ + row * QS2 + ch * 2, Qg + (size_t)row * 128 + ch * 4);
    }
    // KV tile 0
#pragma unroll
    for (int i = 0; i < 8; i++) {
        int idx = i * 256 + tid;
        int row = idx >> 5;
        int ch  = idx & 31;
        cpa16(sK + row * KS2 + ch * 2, Kg + (size_t)row * 128 + ch * 4);
    }
#pragma unroll
    for (int i = 0; i < 8; i++) {
        int idx = i * 256 + tid;
        int d   = idx >> 4;
        int ch  = idx & 15;
        cpa16(sV + d * VS2 + ch * 2, Vg + (size_t)d * 2048 + ch * 4);
    }
    CP_COMMIT;

    float o[16][4];
#pragma unroll
    for (int n = 0; n < 16; n++)
#pragma unroll
        for (int j = 0; j < 4; j++) o[n][j] = 0.f;
    float m0 = -1e30f, m1 = -1e30f, l0 = 0.f, l1 = 0.f;

    const float scale = 0.08838834764831845f;
    const int tmax = 2 * qt + 1;

    for (int t = 0; t <= tmax; t++) {
        const int buf = t & 1;
        if (t < tmax) {
            const int nb2 = (t + 1) & 1;
            float2* dK = sK + nb2 * SK2;
            float2* dV = sV + nb2 * SV2;
            const float* gK = Kg + (size_t)(t + 1) * 64 * 128;
            const float* gV = Vg + (size_t)(t + 1) * 64;
#pragma unroll
            for (int i = 0; i < 8; i++) {
                int idx = i * 256 + tid;
                int row = idx >> 5;
                int ch  = idx & 31;
                cpa16(dK + row * KS2 + ch * 2, gK + (size_t)row * 128 + ch * 4);
            }
#pragma unroll
            for (int i = 0; i < 8; i++) {
                int idx = i * 256 + tid;
                int d   = idx >> 4;
                int ch  = idx & 15;
                cpa16(dV + d * VS2 + ch * 2, gV + (size_t)d * 2048 + ch * 4);
            }
            CP_COMMIT;
            CP_WAIT1;
        } else {
            CP_WAIT0;
        }
        __syncthreads();

        const float2* sKb = sK + buf * SK2;
        const float2* sVb = sV + buf * SV2;

        // ---- S = Q @ K^T, warp tile 16x64, single-pass tf32 ----
        float c[8][4];
#pragma unroll
        for (int n = 0; n < 8; n++)
#pragma unroll
            for (int j = 0; j < 4; j++) c[n][j] = 0.f;

#pragma unroll
        for (int ks = 0; ks < 16; ks++) {
            const float2* qp = sQ + (m_off + lr) * QS2 + ks * 4 + lc;
            float2 q0 = qp[0], q1 = qp[8 * QS2];
            uint32_t a[4] = {u32(q0.x), u32(q1.x), u32(q0.y), u32(q1.y)};
            const float2* kp = sKb + lr * KS2 + ks * 4 + lc;
#pragma unroll
            for (int nf = 0; nf < 8; nf++) {
                float2 bv = kp[nf * 8 * KS2];
                uint32_t b[2] = {u32(bv.x), u32(bv.y)};
                mma8(c[nf], a, b);
            }
        }

        // ---- scale + causal mask ----
#pragma unroll
        for (int nf = 0; nf < 8; nf++)
#pragma unroll
            for (int j = 0; j < 4; j++) c[nf][j] *= scale;

        if (t * 64 + 63 > qt * 128 + m_off) {
#pragma unroll
            for (int nf = 0; nf < 8; nf++) {
#pragma unroll
                for (int j = 0; j < 4; j++) {
                    int col = t * 64 + nf * 8 + 2 * lc + (j & 1);
                    int row = qt * 128 + m_off + lr + 8 * (j >> 1);
                    if (col > row) c[nf][j] = -1e30f;
                }
            }
        }

        // ---- online softmax (rows lr, lr+8) ----
        float mt0 = -1e30f, mt1 = -1e30f;
#pragma unroll
        for (int nf = 0; nf < 8; nf++) {
            mt0 = fmaxf(mt0, fmaxf(c[nf][0], c[nf][1]));
            mt1 = fmaxf(mt1, fmaxf(c[nf][2], c[nf][3]));
        }
#pragma unroll
        for (int d = 1; d <= 2; d <<= 1) {
            mt0 = fmaxf(mt0, __shfl_xor_sync(0xffffffffu, mt0, d));
            mt1 = fmaxf(mt1, __shfl_xor_sync(0xffffffffu, mt1, d));
        }
        float nm0 = fmaxf(m0, mt0), nm1 = fmaxf(m1, mt1);
        float corr0 = __expf(m0 - nm0), corr1 = __expf(m1 - nm1);
        m0 = nm0; m1 = nm1;

        float s0 = 0.f, s1 = 0.f;
#pragma unroll
        for (int nf = 0; nf < 8; nf++) {
            c[nf][0] = __expf(c[nf][0] - nm0); s0 += c[nf][0];
            c[nf][1] = __expf(c[nf][1] - nm0); s0 += c[nf][1];
            c[nf][2] = __expf(c[nf][2] - nm1); s1 += c[nf][2];
            c[nf][3] = __expf(c[nf][3] - nm1); s1 += c[nf][3];
        }
#pragma unroll
        for (int d = 1; d <= 2; d <<= 1) {
            s0 += __shfl_xor_sync(0xffffffffu, s0, d);
            s1 += __shfl_xor_sync(0xffffffffu, s1, d);
        }
        l0 = l0 * corr0 + s0;
        l1 = l1 * corr1 + s1;

#pragma unroll
        for (int n = 0; n < 16; n++) {
            o[n][0] *= corr0; o[n][1] *= corr0;
            o[n][2] *= corr1; o[n][3] *= corr1;
        }

        // ---- O += P @ V, warp tile 16x128, single-pass tf32 ----
#pragma unroll
        for (int ks = 0; ks < 8; ks++) {
            const int src0 = 4 * lr + (lc >> 1);
            const int src1 = src0 + 2;
            float v00 = __shfl_sync(0xffffffffu, c[ks][0], src0);
            float v01 = __shfl_sync(0xffffffffu, c[ks][1], src0);
            float v20 = __shfl_sync(0xffffffffu, c[ks][2], src0);
            float v21 = __shfl_sync(0xffffffffu, c[ks][3], src0);
            float w00 = __shfl_sync(0xffffffffu, c[ks][0], src1);
            float w01 = __shfl_sync(0xffffffffu, c[ks][1], src1);
            float w20 = __shfl_sync(0xffffffffu, c[ks][2], src1);
            float w21 = __shfl_sync(0xffffffffu, c[ks][3], src1);
            float a0f = (lc & 1) ? v01 : v00;
            float a1f = (lc & 1) ? v21 : v20;
            float a2f = (lc & 1) ? w01 : w00;
            float a3f = (lc & 1) ? w21 : w20;
            uint32_t a[4] = {u32(to_tf32(a0f)), u32(to_tf32(a1f)),
                             u32(to_tf32(a2f)), u32(to_tf32(a3f))};
            const float2* vp = sVb + lr * VS2 + ks * 4 + lc;
#pragma unroll
            for (int nf = 0; nf < 16; nf++) {
                float2 bv = vp[nf * 8 * VS2];
                uint32_t b[2] = {u32(bv.x), u32(bv.y)};
                mma8(o[nf], a, b);
            }
        }
        __syncthreads();
    }

    // ---- epilogue: normalize, convert, write pre-paired AP ----
    const float inv0 = 1.0f / l0;
    const float inv1 = 1.0f / l1;
    const int b = bh / Hh;
    const int h = bh % Hh;
    const size_t mrow0 = (size_t)b * 2048 + qt * 128 + m_off + lr;
    const size_t mrow1 = mrow0 + 8;
#pragma unroll
    for (int nf = 0; nf < 16; nf++) {
#pragma unroll
        for (int jj = 0; jj < 2; jj++) {
            int dl = 2 * lc + jj;                         // 0..7 within 8-block
            size_t cslot = (size_t)(h * 16 + nf) * 8 + (dl & 3) * 2 + (dl >> 2);
            AP[mrow0 * 2048 + cslot] = to_tf32(o[nf][jj] * inv0);
            AP[mrow1 * 2048 + cslot] = to_tf32(o[nf][2 + jj] * inv1);
        }
    }
}

// ---------------------------------------------------------------------------

extern "C" void kernel_launch(void* const* d_in, const int* in_sizes, int n_in,
                              void* d_out, int out_size)
{
    const float* x  = (const float*)d_in[0];
    const float* Wq = (const float*)d_in[1];
    const float* bq = (const float*)d_in[2];
    const float* Wk = (const float*)d_in[3];
    const float* bk = (const float*)d_in[4];
    const float* Wv = (const float*)d_in[5];
    const float* bv = (const float*)d_in[6];
    const float* Wd = (const float*)d_in[7];
    const float* bd = (const float*)d_in[8];

    float* out = (float*)d_out;
    float* a_out = out;
    float* k_out = out + (size_t)Bb * Ss * Dd;
    float* v_out = k_out + (size_t)Bb * Ss * Dd;

    float *xp, *wpq, *wpk, *wpv, *wpd, *qp, *kp, *vp, *ap;
    cudaGetSymbolAddress((void**)&xp,  g_XP);
    cudaGetSymbolAddress((void**)&wpq, g_WPq);
    cudaGetSymbolAddress((void**)&wpk, g_WPk);
    cudaGetSymbolAddress((void**)&wpv, g_WPv);
    cudaGetSymbolAddress((void**)&wpd, g_WPd);
    cudaGetSymbolAddress((void**)&qp,  g_QP);
    cudaGetSymbolAddress((void**)&kp,  g_KP);
    cudaGetSymbolAddress((void**)&vp,  g_VP);
    cudaGetSymbolAddress((void**)&ap,  g_AP);

    // prep
    xprep<<<(Mtot * (size_t)Dd / 4) / 256, 256>>>(x, xp);
    wprep<<<((size_t)Dd * Dd / 4) / 256, 256>>>(Wq, wpq);
    wprep<<<((size_t)Dd * Dd / 4) / 256, 256>>>(Wk, wpk);
    wprep<<<((size_t)Dd * Dd / 4) / 256, 256>>>(Wv, wpv);
    wprep<<<((size_t)Dd * Dd / 4) / 256, 256>>>(Wd, wpd);

    dim3 gg(Dd / 128, Mtot / 128);
    size_t gsm = 2 * (size_t)GBUF2 * sizeof(float2);
    cudaFuncSetAttribute(gemm_tc, cudaFuncAttributeMaxDynamicSharedMemorySize, (int)gsm);

    gemm_tc<<<gg, 256, gsm>>>(xp, wpq, bq, nullptr, qp, 1);
    gemm_tc<<<gg, 256, gsm>>>(xp, wpk, bk, k_out, kp, 2);
    gemm_tc<<<gg, 256, gsm>>>(xp, wpv, bv, v_out, vp, 3);

    size_t asm_ = (size_t)(SQ2 + 2 * SK2 + 2 * SV2) * sizeof(float2);
    cudaFuncSetAttribute(attn_tc, cudaFuncAttributeMaxDynamicSharedMemorySize, (int)asm_);
    attn_tc<<<dim3(Ss / 128, Bb * Hh), 256, asm_>>>(qp, kp, vp, ap);

    gemm_tc<<<gg, 256, gsm>>>(ap, wpd, bd, a_out, nullptr, 0);
}